// round 5
// baseline (speedup 1.0000x reference)
#include <cuda_runtime.h>

#define N_PLANES 73
#define BOARD 8
#define FLAT (N_PLANES * BOARD * BOARD)   // 4672
#define N_MOVES 1858
#define BATCH 4096
#define ROWS 2                            // batch rows per gather block
#define E_BLOCKS 296                      // extract blocks
#define NG (BATCH / ROWS)                 // 2048 gather blocks
#define TOTAL (E_BLOCKS + NG)
#define OUT4 ((ROWS * N_MOVES) / 4)       // 929 float4 stores per gather block

// Scratch (device mallocs banned). All state is reset by the last-finishing
// block, so every launch starts from identical state (graph/replay safe).
__device__ __align__(16) int g_idx[N_MOVES];
__device__ int           g_ticket = 0;   // role assignment
__device__ int           g_ctr    = 0;   // extract blocks completed
__device__ int           g_done   = 0;   // all blocks completed
__device__ volatile int  g_flag   = 0;   // idx ready

__global__ __launch_bounds__(256)
void fused_kernel(const float4* __restrict__ W4,
                  const float*  __restrict__ x,
                  float*        __restrict__ out) {
    __shared__ float rows[ROWS * FLAT];   // 37376 B
    __shared__ int   s_ticket;

    const int tid = threadIdx.x;

    // Dynamic role: first E_BLOCKS blocks to start become producers.
    // Producers are resident by definition and wait on nobody -> no deadlock.
    if (tid == 0) s_ticket = atomicAdd(&g_ticket, 1);
    __syncthreads();
    const int ticket = s_ticket;

    if (ticket < E_BLOCKS) {
        // ---------------- producer: scan W, recover one-hot row indices ----
        const int n4 = (FLAT * N_MOVES) / 4;      // 2,170,144
        const int stride = E_BLOCKS * 256;        // 75,776

        for (int base = ticket * 256 + tid; base < n4; base += 4 * stride) {
            int i0 = base;
            int i1 = base + stride;
            int i2 = base + 2 * stride;
            int i3 = base + 3 * stride;
            float4 v0 = __ldcs(&W4[i0]);
            float4 v1 = (i1 < n4) ? __ldcs(&W4[i1]) : make_float4(0.f,0.f,0.f,0.f);
            float4 v2 = (i2 < n4) ? __ldcs(&W4[i2]) : make_float4(0.f,0.f,0.f,0.f);
            float4 v3 = (i3 < n4) ? __ldcs(&W4[i3]) : make_float4(0.f,0.f,0.f,0.f);

            #define CHECK4(v, ii)                                                        \
                if (v.x != 0.f || v.y != 0.f || v.z != 0.f || v.w != 0.f) {              \
                    long e = (long)(ii) * 4;                                             \
                    if (v.x != 0.f) { long t = e;     g_idx[t % N_MOVES] = (int)(t / N_MOVES); } \
                    if (v.y != 0.f) { long t = e + 1; g_idx[t % N_MOVES] = (int)(t / N_MOVES); } \
                    if (v.z != 0.f) { long t = e + 2; g_idx[t % N_MOVES] = (int)(t / N_MOVES); } \
                    if (v.w != 0.f) { long t = e + 3; g_idx[t % N_MOVES] = (int)(t / N_MOVES); } \
                }
            CHECK4(v0, i0)
            CHECK4(v1, i1)
            CHECK4(v2, i2)
            CHECK4(v3, i3)
            #undef CHECK4
        }

        __threadfence();      // publish this thread's g_idx writes
        __syncthreads();      // whole block done before counting
        if (tid == 0) {
            int r = atomicAdd(&g_ctr, 1);
            if (r == E_BLOCKS - 1) {          // last producer
                g_ctr = 0;                    // reset for next launch
                __threadfence();
                g_flag = 1;                   // release consumers
            }
        }
    } else {
        // ---------------- consumer: gather ROWS batch rows ------------------
        const int g = ticket - E_BLOCKS;
        const size_t b0 = (size_t)g * ROWS;

        // Stage rows into smem NOW — overlaps with the W scan.
        const float4* xr = (const float4*)(x + b0 * FLAT);
        float4* rs = (float4*)rows;
        #pragma unroll
        for (int i = tid; i < ROWS * FLAT / 4; i += 256) {
            rs[i] = __ldcs(&xr[i]);
        }
        __syncthreads();

        // Wait for idx to be published.
        if (tid == 0) {
            while (g_flag == 0) { __nanosleep(64); }
            __threadfence();
        }
        __syncthreads();

        // Block's out span is 16B-aligned (2*1858*4 = 14864 ≡ 0 mod 16):
        // 929 contiguous float4 streaming stores.
        float4* ob4 = (float4*)(out + b0 * N_MOVES);
        #pragma unroll
        for (int j = tid; j < OUT4; j += 256) {
            int e0 = 4 * j;
            float v[4];
            #pragma unroll
            for (int k = 0; k < 4; k++) {
                int e = e0 + k;
                int r = (e >= N_MOVES) ? 1 : 0;
                int c = e - r * N_MOVES;
                v[k] = rows[r * FLAT + __ldg(&g_idx[c])];
            }
            __stcs(&ob4[j], make_float4(v[0], v[1], v[2], v[3]));
        }
    }

    // -------- unified completion / state reset (graph-replay safe) ---------
    __syncthreads();
    if (tid == 0) {
        int d = atomicAdd(&g_done, 1);
        if (d == TOTAL - 1) {                 // very last block in launch
            g_done   = 0;
            g_flag   = 0;
            g_ticket = 0;
            __threadfence();
        }
    }
}

extern "C" void kernel_launch(void* const* d_in, const int* in_sizes, int n_in,
                              void* d_out, int out_size) {
    const float* x = (const float*)d_in[0];          // [4096, 73, 8, 8]
    const float* W = (const float*)d_in[1];          // [4672, 1858]
    float* out = (float*)d_out;                      // [4096, 1858]

    fused_kernel<<<TOTAL, 256>>>((const float4*)W, x, out);
}

// round 6
// speedup vs baseline: 1.2744x; 1.2744x over previous
#include <cuda_runtime.h>

#define N_PLANES 73
#define BOARD 8
#define FLAT (N_PLANES * BOARD * BOARD)   // 4672
#define N_MOVES 1858
#define BATCH 4096
#define ROWS 2                            // batch rows per pair
#define NPAIRS (BATCH / ROWS)             // 2048
#define E_BLOCKS 296                      // producer blocks
#define C_BLOCKS 444                      // consumer blocks
#define TOTAL (E_BLOCKS + C_BLOCKS)       // 740 = 148 SMs * 5 blocks
#define OUT4 ((ROWS * N_MOVES) / 4)       // 929 float4 stores per pair
#define PAIR_BYTES (ROWS * FLAT * 4)      // 37376
#define PAIR_LINES (PAIR_BYTES / 128)     // 292

// Scratch (device mallocs banned). All state reset by last-finishing block
// -> identical state every launch (graph/replay safe).
__device__ __align__(16) int g_idx[N_MOVES];
__device__ int           g_ctr  = 0;   // producers completed
__device__ int           g_done = 0;   // all blocks completed
__device__ volatile int  g_flag = 0;   // idx ready

__device__ __forceinline__ void prefetch_l2(const void* p) {
    asm volatile("prefetch.global.L2 [%0];" :: "l"(p));
}

__global__ __launch_bounds__(256, 5)
void fused_kernel(const float4* __restrict__ W4,
                  const float*  __restrict__ x,
                  float*        __restrict__ out) {
    __shared__ float rows[ROWS * FLAT];   // 37376 B

    const int bid = blockIdx.x;
    const int tid = threadIdx.x;

    if (bid < E_BLOCKS) {
        // ---------------- producer: scan W, recover one-hot row indices ----
        const int n4 = (FLAT * N_MOVES) / 4;      // 2,170,144
        const int stride = E_BLOCKS * 256;        // 75,776

        for (int base = bid * 256 + tid; base < n4; base += 4 * stride) {
            int i0 = base;
            int i1 = base + stride;
            int i2 = base + 2 * stride;
            int i3 = base + 3 * stride;
            float4 v0 = __ldcs(&W4[i0]);
            float4 v1 = (i1 < n4) ? __ldcs(&W4[i1]) : make_float4(0.f,0.f,0.f,0.f);
            float4 v2 = (i2 < n4) ? __ldcs(&W4[i2]) : make_float4(0.f,0.f,0.f,0.f);
            float4 v3 = (i3 < n4) ? __ldcs(&W4[i3]) : make_float4(0.f,0.f,0.f,0.f);

            #define CHECK4(v, ii)                                                        \
                if (v.x != 0.f || v.y != 0.f || v.z != 0.f || v.w != 0.f) {              \
                    long e = (long)(ii) * 4;                                             \
                    if (v.x != 0.f) { long t = e;     g_idx[t % N_MOVES] = (int)(t / N_MOVES); } \
                    if (v.y != 0.f) { long t = e + 1; g_idx[t % N_MOVES] = (int)(t / N_MOVES); } \
                    if (v.z != 0.f) { long t = e + 2; g_idx[t % N_MOVES] = (int)(t / N_MOVES); } \
                    if (v.w != 0.f) { long t = e + 3; g_idx[t % N_MOVES] = (int)(t / N_MOVES); } \
                }
            CHECK4(v0, i0)
            CHECK4(v1, i1)
            CHECK4(v2, i2)
            CHECK4(v3, i3)
            #undef CHECK4
        }

        __threadfence();      // publish g_idx writes
        __syncthreads();
        if (tid == 0) {
            int r = atomicAdd(&g_ctr, 1);
            if (r == E_BLOCKS - 1) {          // last producer
                g_ctr = 0;                    // reset for next launch
                __threadfence();
                g_flag = 1;                   // release consumers
            }
        }
    } else {
        // ------- consumer: persistent, owns pairs g, g+C_BLOCKS, ... -------
        const int g = bid - E_BLOCKS;

        // Stage first pair into smem — overlaps the W scan.
        {
            const float4* xr = (const float4*)(x + (size_t)g * ROWS * FLAT);
            float4* rs = (float4*)rows;
            #pragma unroll
            for (int i = tid; i < PAIR_BYTES / 16; i += 256)
                rs[i] = __ldcs(&xr[i]);
        }

        // Prefetch all remaining pairs to L2 — also overlaps the W scan.
        for (int p = g + C_BLOCKS; p < NPAIRS; p += C_BLOCKS) {
            const char* base = (const char*)(x + (size_t)p * ROWS * FLAT);
            for (int i = tid; i < PAIR_LINES; i += 256)
                prefetch_l2(base + i * 128);
        }

        // Wait for idx.
        if (tid == 0) {
            while (g_flag == 0) { __nanosleep(64); }
            __threadfence();
        }
        __syncthreads();   // covers flag + first-pair staging

        int p = g;
        while (true) {
            // 16B-aligned contiguous streaming stores (14864 B per pair).
            float4* ob4 = (float4*)(out + (size_t)p * ROWS * N_MOVES);
            #pragma unroll
            for (int j = tid; j < OUT4; j += 256) {
                int e0 = 4 * j;
                float v[4];
                #pragma unroll
                for (int k = 0; k < 4; k++) {
                    int e = e0 + k;
                    int r = (e >= N_MOVES) ? 1 : 0;
                    int c = e - r * N_MOVES;
                    v[k] = rows[r * FLAT + __ldg(&g_idx[c])];
                }
                __stcs(&ob4[j], make_float4(v[0], v[1], v[2], v[3]));
            }

            p += C_BLOCKS;
            if (p >= NPAIRS) break;

            __syncthreads();   // writes done before smem is overwritten
            {
                const float4* xr = (const float4*)(x + (size_t)p * ROWS * FLAT);
                float4* rs = (float4*)rows;
                #pragma unroll
                for (int i = tid; i < PAIR_BYTES / 16; i += 256)
                    rs[i] = xr[i];           // L2 hit (prefetched)
            }
            __syncthreads();
        }
    }

    // -------- unified completion / state reset (graph-replay safe) ---------
    __syncthreads();
    if (tid == 0) {
        int d = atomicAdd(&g_done, 1);
        if (d == TOTAL - 1) {
            g_done = 0;
            g_flag = 0;
            __threadfence();
        }
    }
}

extern "C" void kernel_launch(void* const* d_in, const int* in_sizes, int n_in,
                              void* d_out, int out_size) {
    const float* x = (const float*)d_in[0];          // [4096, 73, 8, 8]
    const float* W = (const float*)d_in[1];          // [4672, 1858]
    float* out = (float*)d_out;                      // [4096, 1858]

    fused_kernel<<<TOTAL, 256>>>((const float4*)W, x, out);
}